// round 8
// baseline (speedup 1.0000x reference)
#include <cuda_runtime.h>
#include <cstdint>

// ---------------------------------------------------------------------------
// Constants: B=16, T=32, NP=8, NG=4, J=14, H=256
// ---------------------------------------------------------------------------
#define BT         512
#define NP         8
#define NG         4
#define JD         42            // J*3
#define NPERM      1680
#define HM_ELEMS   33554432
#define HM_F4      (HM_ELEMS / 4)     // 8388608 float4
#define HM_BLOCKS  2048
#define TILES      16                 // tiles per heat block
#define TILE_F4    256                // 4KB per tensor per tile
#define STAGES     4
#define NTHREADS   256
#define TOTAL_BLOCKS (BT + HM_BLOCKS)
#define TILE_BYTES (TILE_F4 * 16)     // 4096
#define TX_BYTES   (2 * TILE_BYTES)   // 8192 per stage (pred + gt)

// scratch (device globals — no allocation)
__device__ float g_hm_part[HM_BLOCKS];
__device__ float g_mp_off[BT];
__device__ float g_mp_sz[BT];
__device__ float g_mp_pose[BT];
__device__ unsigned int g_count = 0;   // self-resetting arrival counter

// ---------------------------------------------------------------------------
__device__ __forceinline__ unsigned int fkey(float f) {
    unsigned int u = __float_as_uint(f);
    return (u & 0x80000000u) ? ~u : (u | 0x80000000u);   // order-preserving
}

__device__ __forceinline__ void decode_perm(int p, int r[4]) {
    int avail[8] = {0, 1, 2, 3, 4, 5, 6, 7};
    const int div[4] = {210, 30, 5, 1};
    int n = 8;
    #pragma unroll
    for (int k = 0; k < 4; k++) {
        int idx = p / div[k];
        p -= idx * div[k];
        r[k] = avail[idx];
        for (int m = idx; m < n - 1; m++) avail[m] = avail[m + 1];
        n--;
    }
}

__device__ __forceinline__ double warp_red_d(double v) {
    #pragma unroll
    for (int off = 16; off > 0; off >>= 1)
        v += __shfl_down_sync(0xFFFFFFFFu, v, off);
    return v;
}

__device__ __forceinline__ unsigned int smem_u32(const void* p) {
    unsigned int a;
    asm("{ .reg .u64 t; cvta.to.shared.u64 t, %1; cvt.u32.u64 %0, t; }"
        : "=r"(a) : "l"(p));
    return a;
}

#define MBAR_INIT(addr, cnt) \
    asm volatile("mbarrier.init.shared.b64 [%0], %1;" :: "r"(addr), "r"(cnt) : "memory")

#define MBAR_EXPECT_TX(addr, bytes) \
    asm volatile("mbarrier.arrive.expect_tx.shared.b64 _, [%0], %1;" \
                 :: "r"(addr), "r"(bytes) : "memory")

#define BULK_G2S(dst, src, bytes, mbar) \
    asm volatile("cp.async.bulk.shared::cluster.global.mbarrier::complete_tx::bytes " \
                 "[%0], [%1], %2, [%3];" \
                 :: "r"(dst), "l"(src), "r"(bytes), "r"(mbar) : "memory")

#define FENCE_PROXY_ASYNC() \
    asm volatile("fence.proxy.async.shared::cta;" ::: "memory")

#define MBAR_WAIT_PARITY(addr, parity) do {                                    \
    unsigned int _done = 0;                                                    \
    while (!_done) {                                                           \
        asm volatile("{\n\t.reg .pred p;\n\t"                                  \
            "mbarrier.try_wait.parity.acquire.cta.shared::cta.b64 p, [%1], %2, 0x989680;\n\t" \
            "selp.b32 %0, 1, 0, p;\n\t}"                                       \
            : "=r"(_done) : "r"(addr), "r"(parity) : "memory");                \
    }                                                                          \
} while (0)

// ---------------------------------------------------------------------------
// shared overlay: heat path uses a 4-stage TMA ring; match path small arrays
// ---------------------------------------------------------------------------
struct HeatSmem {
    float4 buf[STAGES][2][TILE_F4];   // 32 KB
    unsigned long long mbar[STAGES];
    float ws[8];
};
struct MatchSmem {
    float pc[NP * 2], gc[NG * 2], sc[NP];
    float po[NP * 2], go[NG * 2];
    float ps[NP * 4], gs[NG * 4];
    float pp[NP * JD], gp[NG * JD];
    float Cb[NP][NG], Cp[NP][NG];
    unsigned long long bestBox, bestPose;
    double wd[8][4];
};

// ---------------------------------------------------------------------------
//   blocks [0, BT)       : Hungarian match for bt = bid  (wave 1, hidden)
//   blocks [BT, TOTAL)   : heatmap MSE via 4-stage TMA pipeline, 16 x 4KB tiles
//   last arriving block  : final reduce + write + reset counter
// ---------------------------------------------------------------------------
__global__ void __launch_bounds__(NTHREADS)
fused_loss_kernel(const float4* __restrict__ hm_pred,
                  const float4* __restrict__ hm_gt,
                  const float* __restrict__ hor_offset,   // [BT,8,2]
                  const float* __restrict__ hor_bsize,    // [BT,8,4]
                  const float* __restrict__ hor_center,   // [BT,8,2]
                  const float* __restrict__ scores,       // [BT,8]
                  const float* __restrict__ x_pose3d,     // [BT,8,42]
                  const float* __restrict__ gt_wh,        // [BT,4,4]
                  const float* __restrict__ gt_off,       // [BT,4,2]
                  const float* __restrict__ gt_center,    // [BT,4,2]
                  const float* __restrict__ gt_pose,      // [BT,4,42]
                  float* __restrict__ out)
{
    const int bid = blockIdx.x;
    const int tid = threadIdx.x;

    __shared__ __align__(16) unsigned char smem_raw[sizeof(HeatSmem) > sizeof(MatchSmem)
                                                    ? sizeof(HeatSmem) : sizeof(MatchSmem)];

    if (bid >= BT) {
        // ============ heatmap MSE: TMA 4-stage pipeline ============
        HeatSmem* sm = reinterpret_cast<HeatSmem*>(smem_raw);
        const int hm_bid = bid - BT;
        const char* srcA = (const char*)(hm_pred + (size_t)hm_bid * TILES * TILE_F4);
        const char* srcB = (const char*)(hm_gt   + (size_t)hm_bid * TILES * TILE_F4);

        unsigned int mb[STAGES];
        #pragma unroll
        for (int s = 0; s < STAGES; s++) mb[s] = smem_u32(&sm->mbar[s]);

        if (tid == 0) {
            #pragma unroll
            for (int s = 0; s < STAGES; s++) MBAR_INIT(mb[s], 1);
        }
        __syncthreads();

        // prologue: fill all 4 stages
        if (tid == 0) {
            #pragma unroll
            for (int s = 0; s < STAGES; s++) {
                MBAR_EXPECT_TX(mb[s], TX_BYTES);
                BULK_G2S(smem_u32(&sm->buf[s][0][0]), srcA + s * TILE_BYTES,
                         TILE_BYTES, mb[s]);
                BULK_G2S(smem_u32(&sm->buf[s][1][0]), srcB + s * TILE_BYTES,
                         TILE_BYTES, mb[s]);
            }
        }

        float s0 = 0.f, s1 = 0.f, s2 = 0.f, s3 = 0.f;
        #pragma unroll
        for (int t = 0; t < TILES; t++) {
            const int st = t & (STAGES - 1);
            const unsigned int parity = (t >> 2) & 1;
            MBAR_WAIT_PARITY(mb[st], parity);

            float4 a = sm->buf[st][0][tid];
            float4 b = sm->buf[st][1][tid];
            float dx = a.x - b.x, dy = a.y - b.y;
            float dz = a.z - b.z, dw = a.w - b.w;
            s0 += dx * dx; s1 += dy * dy; s2 += dz * dz; s3 += dw * dw;

            __syncthreads();   // everyone done with buf[st]
            if (t + STAGES < TILES && tid == 0) {
                FENCE_PROXY_ASYNC();
                MBAR_EXPECT_TX(mb[st], TX_BYTES);
                BULK_G2S(smem_u32(&sm->buf[st][0][0]),
                         srcA + (t + STAGES) * TILE_BYTES, TILE_BYTES, mb[st]);
                BULK_G2S(smem_u32(&sm->buf[st][1][0]),
                         srcB + (t + STAGES) * TILE_BYTES, TILE_BYTES, mb[st]);
            }
        }

        float s = (s0 + s1) + (s2 + s3);
        #pragma unroll
        for (int off = 16; off > 0; off >>= 1)
            s += __shfl_down_sync(0xFFFFFFFFu, s, off);
        int lane = tid & 31, wid = tid >> 5;
        if (lane == 0) sm->ws[wid] = s;
        __syncthreads();
        if (wid == 0) {
            float v = (lane < 8) ? sm->ws[lane] : 0.0f;
            #pragma unroll
            for (int off = 4; off > 0; off >>= 1)
                v += __shfl_down_sync(0xFFFFFFFFu, v, off);
            if (lane == 0) g_hm_part[hm_bid] = v;
        }
    } else {
        // ============ Hungarian match for one (b,t) ============
        MatchSmem* sm = reinterpret_cast<MatchSmem*>(smem_raw);
        const int bt = bid;
        float* pc = sm->pc; float* gc = sm->gc; float* sc = sm->sc;
        float* po = sm->po; float* go = sm->go;
        float* ps = sm->ps; float* gs = sm->gs;
        float* pp = sm->pp; float* gp = sm->gp;

        for (int k = tid; k < NP * 2; k += NTHREADS) pc[k] = hor_center[bt * NP * 2 + k];
        for (int k = tid; k < NG * 2; k += NTHREADS) gc[k] = gt_center[bt * NG * 2 + k];
        for (int k = tid; k < NP;     k += NTHREADS) sc[k] = scores[bt * NP + k];
        for (int k = tid; k < NP * 2; k += NTHREADS) po[k] = hor_offset[bt * NP * 2 + k];
        for (int k = tid; k < NG * 2; k += NTHREADS) go[k] = gt_off[bt * NG * 2 + k];
        for (int k = tid; k < NP * 4; k += NTHREADS) ps[k] = hor_bsize[bt * NP * 4 + k];
        for (int k = tid; k < NG * 4; k += NTHREADS) gs[k] = gt_wh[bt * NG * 4 + k];
        for (int k = tid; k < NP * JD; k += NTHREADS) pp[k] = x_pose3d[bt * NP * JD + k];
        for (int k = tid; k < NG * JD; k += NTHREADS) gp[k] = gt_pose[bt * NG * JD + k];
        if (tid == 0) { sm->bestBox = ~0ULL; sm->bestPose = ~0ULL; }
        __syncthreads();

        if (tid < NP * NG) {
            int i = tid >> 2, j = tid & 3;
            float dx = pc[i * 2 + 0] - gc[j * 2 + 0];
            float dy = pc[i * 2 + 1] - gc[j * 2 + 1];
            sm->Cb[i][j] = sqrtf(dx * dx + dy * dy) - sc[i];
            float acc = 0.0f;
            for (int k = 0; k < JD; k++) {
                float d = pp[i * JD + k] - gp[j * JD + k];
                acc += d * d;
            }
            sm->Cp[i][j] = sqrtf(acc);
        }
        __syncthreads();

        unsigned long long lb = ~0ULL, lp = ~0ULL;
        for (int p = tid; p < NPERM; p += NTHREADS) {
            int r[4];
            decode_perm(p, r);
            float cb = sm->Cb[r[0]][0] + sm->Cb[r[1]][1] + sm->Cb[r[2]][2] + sm->Cb[r[3]][3];
            float cp = sm->Cp[r[0]][0] + sm->Cp[r[1]][1] + sm->Cp[r[2]][2] + sm->Cp[r[3]][3];
            lb = min(lb, ((unsigned long long)fkey(cb) << 32) | (unsigned)p);
            lp = min(lp, ((unsigned long long)fkey(cp) << 32) | (unsigned)p);
        }
        atomicMin(&sm->bestBox, lb);
        atomicMin(&sm->bestPose, lp);
        __syncthreads();

        if (tid == 0) {
            int r[4];
            decode_perm((int)(sm->bestBox & 0xFFFFFFFFu), r);
            float off = 0.0f, sz = 0.0f;
            #pragma unroll
            for (int j = 0; j < NG; j++) {
                int i = r[j];
                off += 0.5f * (fabsf(po[i * 2 + 0] - go[j * 2 + 0]) +
                               fabsf(po[i * 2 + 1] - go[j * 2 + 1]));
                float s4 = 0.0f;
                #pragma unroll
                for (int k = 0; k < 4; k++) s4 += fabsf(ps[i * 4 + k] - gs[j * 4 + k]);
                sz += 0.25f * s4;
            }
            g_mp_off[bt] = off;
            g_mp_sz[bt]  = sz;
        }
        if (tid == 1) {
            int r[4];
            decode_perm((int)(sm->bestPose & 0xFFFFFFFFu), r);
            float s = 0.0f;
            #pragma unroll
            for (int j = 0; j < NG; j++) {
                int i = r[j];
                for (int k = 0; k < JD; k++) {
                    float d = pp[i * JD + k] - gp[j * JD + k];
                    s += d * d;
                }
            }
            g_mp_pose[bt] = s;
        }
    }

    // ---------------- arrival + last-block finalize ----------------
    __syncthreads();
    __shared__ bool isLast;
    if (tid == 0) {
        __threadfence();
        isLast = (atomicAdd(&g_count, 1u) == TOTAL_BLOCKS - 1);
    }
    __syncthreads();
    if (!isLast) return;

    MatchSmem* fm = reinterpret_cast<MatchSmem*>(smem_raw);
    double a0 = 0.0, a1 = 0.0, a2 = 0.0, a3 = 0.0;
    for (int k = tid; k < HM_BLOCKS; k += NTHREADS) a0 += (double)g_hm_part[k];
    for (int k = tid; k < BT; k += NTHREADS) {
        a1 += (double)g_mp_off[k];
        a2 += (double)g_mp_sz[k];
        a3 += (double)g_mp_pose[k];
    }
    a0 = warp_red_d(a0); a1 = warp_red_d(a1); a2 = warp_red_d(a2); a3 = warp_red_d(a3);
    int lane = tid & 31, wid = tid >> 5;
    if (lane == 0) { fm->wd[wid][0] = a0; fm->wd[wid][1] = a1;
                     fm->wd[wid][2] = a2; fm->wd[wid][3] = a3; }
    __syncthreads();
    if (wid == 0) {
        double v0 = (lane < 8) ? fm->wd[lane][0] : 0.0;
        double v1 = (lane < 8) ? fm->wd[lane][1] : 0.0;
        double v2 = (lane < 8) ? fm->wd[lane][2] : 0.0;
        double v3 = (lane < 8) ? fm->wd[lane][3] : 0.0;
        #pragma unroll
        for (int off = 4; off > 0; off >>= 1) {
            v0 += __shfl_down_sync(0xFFFFFFFFu, v0, off);
            v1 += __shfl_down_sync(0xFFFFFFFFu, v1, off);
            v2 += __shfl_down_sync(0xFFFFFFFFu, v2, off);
            v3 += __shfl_down_sync(0xFFFFFFFFu, v3, off);
        }
        if (lane == 0) {
            double center = v0 / (double)HM_ELEMS;
            double offL   = v1 / (double)BT;
            double szL    = v2 / (double)BT;
            double poseL  = v3 / (double)(BT * NP * 14);
            out[0] = (float)(center + offL + szL + poseL);
            g_count = 0;   // reset for next graph replay
        }
    }
}

extern "C" void kernel_launch(void* const* d_in, const int* in_sizes, int n_in,
                              void* d_out, int out_size) {
    const float* hor_heatmap = (const float*)d_in[0];
    const float* hor_offset  = (const float*)d_in[1];
    const float* hor_bsize   = (const float*)d_in[2];
    const float* hor_center  = (const float*)d_in[3];
    const float* scores      = (const float*)d_in[4];
    const float* x_pose3d    = (const float*)d_in[5];
    const float* gt_heatmap  = (const float*)d_in[6];
    const float* gt_wh       = (const float*)d_in[7];
    const float* gt_off      = (const float*)d_in[8];
    const float* gt_center   = (const float*)d_in[9];
    const float* gt_pose     = (const float*)d_in[10];
    float* out = (float*)d_out;

    fused_loss_kernel<<<TOTAL_BLOCKS, NTHREADS>>>(
        (const float4*)hor_heatmap, (const float4*)gt_heatmap,
        hor_offset, hor_bsize, hor_center, scores, x_pose3d,
        gt_wh, gt_off, gt_center, gt_pose, out);
}

// round 9
// speedup vs baseline: 1.0367x; 1.0367x over previous
#include <cuda_runtime.h>
#include <cstdint>

// ---------------------------------------------------------------------------
// Constants: B=16, T=32, NP=8, NG=4, J=14, H=256
// ---------------------------------------------------------------------------
#define BT         512
#define NP         8
#define NG         4
#define JD         42            // J*3
#define NPERM      1680
#define HM_ELEMS   33554432
#define HM_F4      (HM_ELEMS / 4)     // 8388608 float4
#define HM_BLOCKS  2048
#define TILES      16                 // tiles per heat block
#define TILE_F4    256                // 4KB per tensor per tile
#define STAGES     4
#define NCONS      256                // consumer threads
#define NTHREADS   288                // + producer warp
#define TOTAL_BLOCKS (BT + HM_BLOCKS)
#define TILE_BYTES (TILE_F4 * 16)     // 4096
#define TX_BYTES   (2 * TILE_BYTES)   // 8192 per stage (pred + gt)

// scratch (device globals — no allocation)
__device__ float g_hm_part[HM_BLOCKS];
__device__ float g_mp_off[BT];
__device__ float g_mp_sz[BT];
__device__ float g_mp_pose[BT];
__device__ unsigned int g_count = 0;   // self-resetting arrival counter

// ---------------------------------------------------------------------------
__device__ __forceinline__ unsigned int fkey(float f) {
    unsigned int u = __float_as_uint(f);
    return (u & 0x80000000u) ? ~u : (u | 0x80000000u);   // order-preserving
}

__device__ __forceinline__ void decode_perm(int p, int r[4]) {
    int avail[8] = {0, 1, 2, 3, 4, 5, 6, 7};
    const int div[4] = {210, 30, 5, 1};
    int n = 8;
    #pragma unroll
    for (int k = 0; k < 4; k++) {
        int idx = p / div[k];
        p -= idx * div[k];
        r[k] = avail[idx];
        for (int m = idx; m < n - 1; m++) avail[m] = avail[m + 1];
        n--;
    }
}

__device__ __forceinline__ double warp_red_d(double v) {
    #pragma unroll
    for (int off = 16; off > 0; off >>= 1)
        v += __shfl_down_sync(0xFFFFFFFFu, v, off);
    return v;
}

__device__ __forceinline__ unsigned int smem_u32(const void* p) {
    unsigned int a;
    asm("{ .reg .u64 t; cvta.to.shared.u64 t, %1; cvt.u32.u64 %0, t; }"
        : "=r"(a) : "l"(p));
    return a;
}

#define MBAR_INIT(addr, cnt) \
    asm volatile("mbarrier.init.shared.b64 [%0], %1;" :: "r"(addr), "r"(cnt) : "memory")

#define MBAR_EXPECT_TX(addr, bytes) \
    asm volatile("mbarrier.arrive.expect_tx.shared.b64 _, [%0], %1;" \
                 :: "r"(addr), "r"(bytes) : "memory")

#define MBAR_ARRIVE(addr) \
    asm volatile("mbarrier.arrive.shared.b64 _, [%0];" :: "r"(addr) : "memory")

#define BULK_G2S(dst, src, bytes, mbar) \
    asm volatile("cp.async.bulk.shared::cluster.global.mbarrier::complete_tx::bytes " \
                 "[%0], [%1], %2, [%3];" \
                 :: "r"(dst), "l"(src), "r"(bytes), "r"(mbar) : "memory")

#define MBAR_WAIT_PARITY(addr, parity) do {                                    \
    unsigned int _done = 0;                                                    \
    while (!_done) {                                                           \
        asm volatile("{\n\t.reg .pred p;\n\t"                                  \
            "mbarrier.try_wait.parity.acquire.cta.shared::cta.b64 p, [%1], %2, 0x989680;\n\t" \
            "selp.b32 %0, 1, 0, p;\n\t}"                                       \
            : "=r"(_done) : "r"(addr), "r"(parity) : "memory");                \
    }                                                                          \
} while (0)

#define MBAR_WAIT_PARITY_RELAXED(addr, parity) do {                            \
    unsigned int _done = 0;                                                    \
    while (!_done) {                                                           \
        asm volatile("{\n\t.reg .pred p;\n\t"                                  \
            "mbarrier.try_wait.parity.relaxed.cta.shared::cta.b64 p, [%1], %2, 0x989680;\n\t" \
            "selp.b32 %0, 1, 0, p;\n\t}"                                       \
            : "=r"(_done) : "r"(addr), "r"(parity) : "memory");                \
    }                                                                          \
} while (0)

// ---------------------------------------------------------------------------
struct HeatSmem {
    float4 buf[STAGES][2][TILE_F4];        // 32 KB
    unsigned long long full[STAGES];
    unsigned long long empty[STAGES];
    float ws[8];
};
struct MatchSmem {
    float pc[NP * 2], gc[NG * 2], sc[NP];
    float po[NP * 2], go[NG * 2];
    float ps[NP * 4], gs[NG * 4];
    float pp[NP * JD], gp[NG * JD];
    float Cb[NP][NG], Cp[NP][NG];
    unsigned long long bestBox, bestPose;
};

// ---------------------------------------------------------------------------
//   blocks [0, BT)       : Hungarian match for bt = bid  (wave 1, hidden)
//   blocks [BT, TOTAL)   : heatmap MSE, warp-specialized TMA pipeline
//   last arriving block  : final reduce + write + reset counter
// ---------------------------------------------------------------------------
__global__ void __launch_bounds__(NTHREADS)
fused_loss_kernel(const float4* __restrict__ hm_pred,
                  const float4* __restrict__ hm_gt,
                  const float* __restrict__ hor_offset,   // [BT,8,2]
                  const float* __restrict__ hor_bsize,    // [BT,8,4]
                  const float* __restrict__ hor_center,   // [BT,8,2]
                  const float* __restrict__ scores,       // [BT,8]
                  const float* __restrict__ x_pose3d,     // [BT,8,42]
                  const float* __restrict__ gt_wh,        // [BT,4,4]
                  const float* __restrict__ gt_off,       // [BT,4,2]
                  const float* __restrict__ gt_center,    // [BT,4,2]
                  const float* __restrict__ gt_pose,      // [BT,4,42]
                  float* __restrict__ out)
{
    const int bid = blockIdx.x;
    const int tid = threadIdx.x;

    __shared__ __align__(16) unsigned char smem_raw[sizeof(HeatSmem) > sizeof(MatchSmem)
                                                    ? sizeof(HeatSmem) : sizeof(MatchSmem)];
    __shared__ double s_wd[9][4];

    if (bid >= BT) {
        // ============ heatmap MSE: producer/consumer TMA pipeline ============
        HeatSmem* sm = reinterpret_cast<HeatSmem*>(smem_raw);
        const int hm_bid = bid - BT;
        const char* srcA = (const char*)(hm_pred + (size_t)hm_bid * TILES * TILE_F4);
        const char* srcB = (const char*)(hm_gt   + (size_t)hm_bid * TILES * TILE_F4);

        unsigned int fb[STAGES], eb[STAGES];
        #pragma unroll
        for (int s = 0; s < STAGES; s++) {
            fb[s] = smem_u32(&sm->full[s]);
            eb[s] = smem_u32(&sm->empty[s]);
        }

        if (tid == 0) {
            #pragma unroll
            for (int s = 0; s < STAGES; s++) {
                MBAR_INIT(fb[s], 1);     // producer's expect_tx arrive
                MBAR_INIT(eb[s], 8);     // one elected arrive per consumer warp
            }
        }
        __syncthreads();

        if (tid < NCONS) {
            // ---------------- consumers (warps 0-7) ----------------
            float s0 = 0.f, s1 = 0.f, s2 = 0.f, s3 = 0.f;
            #pragma unroll
            for (int t = 0; t < TILES; t++) {
                const int st = t & (STAGES - 1);
                const unsigned int parity = (t >> 2) & 1;
                MBAR_WAIT_PARITY(fb[st], parity);

                float4 a = sm->buf[st][0][tid];
                float4 b = sm->buf[st][1][tid];
                float dx = a.x - b.x, dy = a.y - b.y;
                float dz = a.z - b.z, dw = a.w - b.w;
                s0 += dx * dx; s1 += dy * dy; s2 += dz * dz; s3 += dw * dw;

                __syncwarp();
                if ((tid & 31) == 0) MBAR_ARRIVE(eb[st]);
            }
            float s = (s0 + s1) + (s2 + s3);
            #pragma unroll
            for (int off = 16; off > 0; off >>= 1)
                s += __shfl_down_sync(0xFFFFFFFFu, s, off);
            if ((tid & 31) == 0) sm->ws[tid >> 5] = s;
        } else if (tid == NCONS) {
            // ---------------- producer (warp 8, lane 0) ----------------
            for (int t = 0; t < TILES; t++) {
                const int st = t & (STAGES - 1);
                if (t >= STAGES) {
                    const unsigned int parity = ((t - STAGES) >> 2) & 1;
                    MBAR_WAIT_PARITY_RELAXED(eb[st], parity);
                }
                MBAR_EXPECT_TX(fb[st], TX_BYTES);
                BULK_G2S(smem_u32(&sm->buf[st][0][0]),
                         srcA + (size_t)t * TILE_BYTES, TILE_BYTES, fb[st]);
                BULK_G2S(smem_u32(&sm->buf[st][1][0]),
                         srcB + (size_t)t * TILE_BYTES, TILE_BYTES, fb[st]);
            }
        }
        __syncthreads();
        if (tid < 32) {
            float v = (tid < 8) ? sm->ws[tid] : 0.0f;
            #pragma unroll
            for (int off = 4; off > 0; off >>= 1)
                v += __shfl_down_sync(0xFFFFFFFFu, v, off);
            if (tid == 0) g_hm_part[hm_bid] = v;
        }
    } else {
        // ============ Hungarian match for one (b,t) ============
        MatchSmem* sm = reinterpret_cast<MatchSmem*>(smem_raw);
        const int bt = bid;
        float* pc = sm->pc; float* gc = sm->gc; float* sc = sm->sc;
        float* po = sm->po; float* go = sm->go;
        float* ps = sm->ps; float* gs = sm->gs;
        float* pp = sm->pp; float* gp = sm->gp;

        for (int k = tid; k < NP * 2; k += NTHREADS) pc[k] = hor_center[bt * NP * 2 + k];
        for (int k = tid; k < NG * 2; k += NTHREADS) gc[k] = gt_center[bt * NG * 2 + k];
        for (int k = tid; k < NP;     k += NTHREADS) sc[k] = scores[bt * NP + k];
        for (int k = tid; k < NP * 2; k += NTHREADS) po[k] = hor_offset[bt * NP * 2 + k];
        for (int k = tid; k < NG * 2; k += NTHREADS) go[k] = gt_off[bt * NG * 2 + k];
        for (int k = tid; k < NP * 4; k += NTHREADS) ps[k] = hor_bsize[bt * NP * 4 + k];
        for (int k = tid; k < NG * 4; k += NTHREADS) gs[k] = gt_wh[bt * NG * 4 + k];
        for (int k = tid; k < NP * JD; k += NTHREADS) pp[k] = x_pose3d[bt * NP * JD + k];
        for (int k = tid; k < NG * JD; k += NTHREADS) gp[k] = gt_pose[bt * NG * JD + k];
        if (tid == 0) { sm->bestBox = ~0ULL; sm->bestPose = ~0ULL; }
        __syncthreads();

        if (tid < NP * NG) {
            int i = tid >> 2, j = tid & 3;
            float dx = pc[i * 2 + 0] - gc[j * 2 + 0];
            float dy = pc[i * 2 + 1] - gc[j * 2 + 1];
            sm->Cb[i][j] = sqrtf(dx * dx + dy * dy) - sc[i];
            float acc = 0.0f;
            for (int k = 0; k < JD; k++) {
                float d = pp[i * JD + k] - gp[j * JD + k];
                acc += d * d;
            }
            sm->Cp[i][j] = sqrtf(acc);
        }
        __syncthreads();

        unsigned long long lb = ~0ULL, lp = ~0ULL;
        for (int p = tid; p < NPERM; p += NTHREADS) {
            int r[4];
            decode_perm(p, r);
            float cb = sm->Cb[r[0]][0] + sm->Cb[r[1]][1] + sm->Cb[r[2]][2] + sm->Cb[r[3]][3];
            float cp = sm->Cp[r[0]][0] + sm->Cp[r[1]][1] + sm->Cp[r[2]][2] + sm->Cp[r[3]][3];
            lb = min(lb, ((unsigned long long)fkey(cb) << 32) | (unsigned)p);
            lp = min(lp, ((unsigned long long)fkey(cp) << 32) | (unsigned)p);
        }
        atomicMin(&sm->bestBox, lb);
        atomicMin(&sm->bestPose, lp);
        __syncthreads();

        if (tid == 0) {
            int r[4];
            decode_perm((int)(sm->bestBox & 0xFFFFFFFFu), r);
            float off = 0.0f, sz = 0.0f;
            #pragma unroll
            for (int j = 0; j < NG; j++) {
                int i = r[j];
                off += 0.5f * (fabsf(po[i * 2 + 0] - go[j * 2 + 0]) +
                               fabsf(po[i * 2 + 1] - go[j * 2 + 1]));
                float s4 = 0.0f;
                #pragma unroll
                for (int k = 0; k < 4; k++) s4 += fabsf(ps[i * 4 + k] - gs[j * 4 + k]);
                sz += 0.25f * s4;
            }
            g_mp_off[bt] = off;
            g_mp_sz[bt]  = sz;
        }
        if (tid == 1) {
            int r[4];
            decode_perm((int)(sm->bestPose & 0xFFFFFFFFu), r);
            float s = 0.0f;
            #pragma unroll
            for (int j = 0; j < NG; j++) {
                int i = r[j];
                for (int k = 0; k < JD; k++) {
                    float d = pp[i * JD + k] - gp[j * JD + k];
                    s += d * d;
                }
            }
            g_mp_pose[bt] = s;
        }
    }

    // ---------------- arrival + last-block finalize ----------------
    __syncthreads();
    __shared__ bool isLast;
    if (tid == 0) {
        __threadfence();
        isLast = (atomicAdd(&g_count, 1u) == TOTAL_BLOCKS - 1);
    }
    __syncthreads();
    if (!isLast) return;

    double a0 = 0.0, a1 = 0.0, a2 = 0.0, a3 = 0.0;
    for (int k = tid; k < HM_BLOCKS; k += NTHREADS) a0 += (double)g_hm_part[k];
    for (int k = tid; k < BT; k += NTHREADS) {
        a1 += (double)g_mp_off[k];
        a2 += (double)g_mp_sz[k];
        a3 += (double)g_mp_pose[k];
    }
    a0 = warp_red_d(a0); a1 = warp_red_d(a1); a2 = warp_red_d(a2); a3 = warp_red_d(a3);
    int lane = tid & 31, wid = tid >> 5;   // 9 warps
    if (lane == 0) { s_wd[wid][0] = a0; s_wd[wid][1] = a1;
                     s_wd[wid][2] = a2; s_wd[wid][3] = a3; }
    __syncthreads();
    if (wid == 0) {
        double v0 = (lane < 9) ? s_wd[lane][0] : 0.0;
        double v1 = (lane < 9) ? s_wd[lane][1] : 0.0;
        double v2 = (lane < 9) ? s_wd[lane][2] : 0.0;
        double v3 = (lane < 9) ? s_wd[lane][3] : 0.0;
        #pragma unroll
        for (int off = 8; off > 0; off >>= 1) {
            v0 += __shfl_down_sync(0xFFFFFFFFu, v0, off);
            v1 += __shfl_down_sync(0xFFFFFFFFu, v1, off);
            v2 += __shfl_down_sync(0xFFFFFFFFu, v2, off);
            v3 += __shfl_down_sync(0xFFFFFFFFu, v3, off);
        }
        if (lane == 0) {
            double center = v0 / (double)HM_ELEMS;
            double offL   = v1 / (double)BT;
            double szL    = v2 / (double)BT;
            double poseL  = v3 / (double)(BT * NP * 14);
            out[0] = (float)(center + offL + szL + poseL);
            g_count = 0;   // reset for next graph replay
        }
    }
}

extern "C" void kernel_launch(void* const* d_in, const int* in_sizes, int n_in,
                              void* d_out, int out_size) {
    const float* hor_heatmap = (const float*)d_in[0];
    const float* hor_offset  = (const float*)d_in[1];
    const float* hor_bsize   = (const float*)d_in[2];
    const float* hor_center  = (const float*)d_in[3];
    const float* scores      = (const float*)d_in[4];
    const float* x_pose3d    = (const float*)d_in[5];
    const float* gt_heatmap  = (const float*)d_in[6];
    const float* gt_wh       = (const float*)d_in[7];
    const float* gt_off      = (const float*)d_in[8];
    const float* gt_center   = (const float*)d_in[9];
    const float* gt_pose     = (const float*)d_in[10];
    float* out = (float*)d_out;

    fused_loss_kernel<<<TOTAL_BLOCKS, NTHREADS>>>(
        (const float4*)hor_heatmap, (const float4*)gt_heatmap,
        hor_offset, hor_bsize, hor_center, scores, x_pose3d,
        gt_wh, gt_off, gt_center, gt_pose, out);
}